// round 1
// baseline (speedup 1.0000x reference)
#include <cuda_runtime.h>

// EfficientGNN: 2-layer GCN with mean-over-nodes output.
// Algebraic reduction:
//   s[c] = sum_{e: col=c} norm_e * x[row_e]          (scalar per node, incl. self loop)
//   w[r] = sum_{e: row=r} norm_e                     (scalar per node, incl. self loop)
//   h1[r,f] = relu(s[r]*W1[f] + b1[f])
//   t[f]  = sum_r w[r] * h1[r,f]                     (128-vector)
//   out[k] = (t @ W2)[k] / N + b2[k]                 (400-vector)

#define NMAX 100000
#define HID  128

__device__ float g_dinv[NMAX];   // deg during pass 1, then d^-1/2
__device__ float g_s[NMAX];
__device__ float g_w[NMAX];
__device__ float g_t[HID];

__global__ void k_init(int n) {
    int i = blockIdx.x * blockDim.x + threadIdx.x;
    if (i < n)   g_dinv[i] = 1.0f;     // self-loop baseline for degree
    if (i < HID) g_t[i] = 0.0f;
}

__global__ void k_deg(const int* __restrict__ col, int E) {
    int e = blockIdx.x * blockDim.x + threadIdx.x;
    if (e < E) atomicAdd(&g_dinv[col[e]], 1.0f);
}

// deg -> dinv, and fold in the self-loop contribution to s and w (plain stores,
// runs before the edge atomics kernel).
__global__ void k_dinv_self(const float* __restrict__ x, int n) {
    int i = blockIdx.x * blockDim.x + threadIdx.x;
    if (i < n) {
        float d  = rsqrtf(g_dinv[i]);
        g_dinv[i] = d;
        float d2 = d * d;                 // norm of self loop (i,i)
        g_s[i] = d2 * x[i];
        g_w[i] = d2;
    }
}

__global__ void k_edge(const int* __restrict__ row, const int* __restrict__ col,
                       const float* __restrict__ x, int E) {
    int e = blockIdx.x * blockDim.x + threadIdx.x;
    if (e < E) {
        int r = row[e];
        int c = col[e];
        float nrm = g_dinv[r] * g_dinv[c];
        atomicAdd(&g_s[c], nrm * __ldg(&x[r]));
        atomicAdd(&g_w[r], nrm);
    }
}

// t[f] = sum_i w[i] * relu(s[i]*W1[f] + b1[f]);  blockDim.x == HID
__global__ void k_reduce(const float* __restrict__ W1, const float* __restrict__ b1, int n) {
    __shared__ float sh_s[HID];
    __shared__ float sh_w[HID];
    int f = threadIdx.x;
    float W1f = W1[f];
    float b1f = b1[f];
    float acc = 0.0f;
    for (int base = blockIdx.x * HID; base < n; base += gridDim.x * HID) {
        int tile = n - base;
        if (tile > HID) tile = HID;
        if (f < tile) {
            sh_s[f] = g_s[base + f];
            sh_w[f] = g_w[base + f];
        }
        __syncthreads();
        #pragma unroll 8
        for (int j = 0; j < tile; ++j)
            acc += sh_w[j] * fmaxf(fmaf(sh_s[j], W1f, b1f), 0.0f);
        __syncthreads();
    }
    atomicAdd(&g_t[f], acc);
}

// out[k] = dot(t, W2[:,k]) / n + b2[k];  single block
__global__ void k_out(const float* __restrict__ W2, const float* __restrict__ b2,
                      float* __restrict__ out, int n, int odim) {
    __shared__ float sh_t[HID];
    if (threadIdx.x < HID) sh_t[threadIdx.x] = g_t[threadIdx.x];
    __syncthreads();
    int k = threadIdx.x;
    if (k < odim) {
        float acc = 0.0f;
        #pragma unroll 16
        for (int f = 0; f < HID; ++f)
            acc = fmaf(sh_t[f], W2[f * odim + k], acc);
        out[k] = acc * (1.0f / (float)n) + b2[k];
    }
}

extern "C" void kernel_launch(void* const* d_in, const int* in_sizes, int n_in,
                              void* d_out, int out_size) {
    const float* x   = (const float*)d_in[0];
    const int*   ei  = (const int*)  d_in[1];
    const float* W1  = (const float*)d_in[2];
    const float* b1  = (const float*)d_in[3];
    const float* W2  = (const float*)d_in[4];
    const float* b2  = (const float*)d_in[5];
    float*       out = (float*)d_out;

    int n = in_sizes[0];            // 100000 (x is [N,1])
    int E = in_sizes[1] / 2;        // edge_index is [2,E]
    const int* row = ei;
    const int* col = ei + E;
    int odim = out_size;            // 400

    int tb = 256;
    k_init     <<<(n + tb - 1) / tb, tb>>>(n);
    k_deg      <<<(E + tb - 1) / tb, tb>>>(col, E);
    k_dinv_self<<<(n + tb - 1) / tb, tb>>>(x, n);
    k_edge     <<<(E + tb - 1) / tb, tb>>>(row, col, x, E);
    k_reduce   <<<512, HID>>>(W1, b1, n);
    k_out      <<<1, 512>>>(W2, b2, out, n, odim);
}

// round 2
// speedup vs baseline: 1.0212x; 1.0212x over previous
#include <cuda_runtime.h>

// EfficientGNN: 2-layer GCN + mean-over-nodes, algebraically collapsed.
//   deg[c]  = #edges into c (+1 self loop)
//   dinv[i] = rsqrt(deg[i]);  p[i] = dinv[i]*x[i]
//   u[c]    = sum_{e->c} p[row_e]        (random RED)
//   v[r]    = sum_{e from r} dinv[col_e] (random RED)
//   s[i]    = dinv[i]*(dinv[i]*x[i] + u[i])   // incl self loop
//   w[i]    = dinv[i]*(dinv[i]      + v[i])
//   t[f]    = sum_i w[i]*relu(s[i]*W1[f]+b1[f])
//   out[k]  = (t@W2)[k]/N + b2[k]

#define NMAX 100000
#define HID  128

// one contiguous accumulator block -> single memset
// layout: [0:N) deg, [N:2N) u, [2N:3N) v, [3N:3N+HID) t
__device__ float g_acc[3 * NMAX + HID];
__device__ float g_dinv[NMAX];
__device__ float g_p[NMAX];

__global__ void k_deg(const int* __restrict__ col, int E) {
    float* deg = g_acc;
    int i = blockIdx.x * blockDim.x + threadIdx.x;
    int e0 = i * 4;
    if (e0 + 3 < E) {
        int4 c = *reinterpret_cast<const int4*>(col + e0);
        atomicAdd(&deg[c.x], 1.0f);
        atomicAdd(&deg[c.y], 1.0f);
        atomicAdd(&deg[c.z], 1.0f);
        atomicAdd(&deg[c.w], 1.0f);
    } else {
        for (int e = e0; e < E; ++e) atomicAdd(&deg[col[e]], 1.0f);
    }
}

__global__ void k_dinv(const float* __restrict__ x, int n) {
    int i = blockIdx.x * blockDim.x + threadIdx.x;
    if (i < n) {
        float d = rsqrtf(g_acc[i] + 1.0f);   // +1 self loop
        g_dinv[i] = d;
        g_p[i]    = d * x[i];
    }
}

__global__ void k_edge(const int* __restrict__ row, const int* __restrict__ col, int E) {
    float* u = g_acc + NMAX;
    float* v = g_acc + 2 * NMAX;
    int i = blockIdx.x * blockDim.x + threadIdx.x;
    int e0 = i * 4;
    if (e0 + 3 < E) {
        int4 r = *reinterpret_cast<const int4*>(row + e0);
        int4 c = *reinterpret_cast<const int4*>(col + e0);
        // issue all gathers first (MLP), then the REDs
        float p0 = g_p[r.x], p1 = g_p[r.y], p2 = g_p[r.z], p3 = g_p[r.w];
        float d0 = g_dinv[c.x], d1 = g_dinv[c.y], d2 = g_dinv[c.z], d3 = g_dinv[c.w];
        atomicAdd(&u[c.x], p0);
        atomicAdd(&u[c.y], p1);
        atomicAdd(&u[c.z], p2);
        atomicAdd(&u[c.w], p3);
        atomicAdd(&v[r.x], d0);
        atomicAdd(&v[r.y], d1);
        atomicAdd(&v[r.z], d2);
        atomicAdd(&v[r.w], d3);
    } else {
        for (int e = e0; e < E; ++e) {
            int r = row[e], c = col[e];
            atomicAdd(&u[c], g_p[r]);
            atomicAdd(&v[r], g_dinv[c]);
        }
    }
}

// t[f] = sum_i w[i]*relu(s[i]*W1[f]+b1[f]);  blockDim.x == HID
__global__ void k_reduce(const float* __restrict__ x,
                         const float* __restrict__ W1, const float* __restrict__ b1, int n) {
    const float* u = g_acc + NMAX;
    const float* v = g_acc + 2 * NMAX;
    float* t = g_acc + 3 * NMAX;
    __shared__ float sh_s[HID];
    __shared__ float sh_w[HID];
    int f = threadIdx.x;
    float W1f = W1[f];
    float b1f = b1[f];
    float acc = 0.0f;
    for (int base = blockIdx.x * HID; base < n; base += gridDim.x * HID) {
        int tile = n - base;
        if (tile > HID) tile = HID;
        if (f < tile) {
            int i = base + f;
            float d  = g_dinv[i];
            float xx = x[i];
            sh_s[f] = d * fmaf(d, xx, u[i]);
            sh_w[f] = d * (d + v[i]);
        }
        __syncthreads();
        #pragma unroll 8
        for (int j = 0; j < tile; ++j)
            acc += sh_w[j] * fmaxf(fmaf(sh_s[j], W1f, b1f), 0.0f);
        __syncthreads();
    }
    atomicAdd(&t[f], acc);
}

__global__ void k_out(const float* __restrict__ W2, const float* __restrict__ b2,
                      float* __restrict__ out, int n, int odim) {
    const float* t = g_acc + 3 * NMAX;
    __shared__ float sh_t[HID];
    if (threadIdx.x < HID) sh_t[threadIdx.x] = t[threadIdx.x];
    __syncthreads();
    int k = threadIdx.x;
    if (k < odim) {
        float acc = 0.0f;
        #pragma unroll 16
        for (int f = 0; f < HID; ++f)
            acc = fmaf(sh_t[f], W2[f * odim + k], acc);
        out[k] = acc * (1.0f / (float)n) + b2[k];
    }
}

extern "C" void kernel_launch(void* const* d_in, const int* in_sizes, int n_in,
                              void* d_out, int out_size) {
    const float* x   = (const float*)d_in[0];
    const int*   ei  = (const int*)  d_in[1];
    const float* W1  = (const float*)d_in[2];
    const float* b1  = (const float*)d_in[3];
    const float* W2  = (const float*)d_in[4];
    const float* b2  = (const float*)d_in[5];
    float*       out = (float*)d_out;

    int n = in_sizes[0];
    int E = in_sizes[1] / 2;
    const int* row = ei;
    const int* col = ei + E;
    int odim = out_size;

    void* accp = nullptr;
    cudaGetSymbolAddress(&accp, g_acc);
    cudaMemsetAsync(accp, 0, (3 * NMAX + HID) * sizeof(float), 0);

    int tb = 256;
    int e4 = (E + 3) / 4;
    k_deg   <<<(e4 + tb - 1) / tb, tb>>>(col, E);
    k_dinv  <<<(n + tb - 1) / tb, tb>>>(x, n);
    k_edge  <<<(e4 + tb - 1) / tb, tb>>>(row, col, E);
    k_reduce<<<512, HID>>>(x, W1, b1, n);
    k_out   <<<1, 512>>>(W2, b2, out, n, odim);
}